// round 1
// baseline (speedup 1.0000x reference)
#include <cuda_runtime.h>

#define GPB 32         // graphs per block
#define NTHREADS 256   // 8 threads per graph

// Dynamic shared layout (floats):
//   Wl1s : 64*132  = 8448   (padded stride 132 -> conflict-free rows)
//   hs   : 32*132  = 4224   (per-graph node features, stride 132)
//   zs   : 32*68   = 2176
//   Wl2s : 16*68   = 1088
//   Wcs  : 176               (W1[8] @0, W2[32] @8, W3[128] @40)
//   bcs  : 32                (b1[4] @0, b2[8] @4, b3[16] @12)
//   bl1s : 64
//   bl2s : 16
//   es   : 1024 ints
#define SMEM_FLOATS (8448 + 4224 + 2176 + 1088 + 176 + 32 + 64 + 16 + 1024)
#define SMEM_BYTES  (SMEM_FLOATS * 4)

template<int Cin, int Cout>
__device__ __forceinline__ void gcn_layer(
    const float* __restrict__ Wsh, const float* __restrict__ bsh,
    const float* hin, float* hout, float* hsg, int n, float dis,
    unsigned rl, unsigned rh, unsigned cl, unsigned ch)
{
    // h = x @ W^T, pre-scaled by dis[n]
    float t[Cout];
#pragma unroll
    for (int c = 0; c < Cout; c++) {
        float a = 0.f;
#pragma unroll
        for (int k = 0; k < Cin; k++) a = fmaf(Wsh[c * Cin + k], hin[k], a);
        t[c] = dis * a;
    }
    // publish scaled features (node stride 16 floats, 16B aligned)
#pragma unroll
    for (int c = 0; c < Cout; c += 4)
        *((float4*)(hsg + n * 16 + c)) = make_float4(t[c], t[c + 1], t[c + 2], t[c + 3]);
    __syncthreads();

    // aggregate: self-loop from registers + matching edges from shared
    float acc[Cout];
#pragma unroll
    for (int c = 0; c < Cout; c++) acc[c] = t[c];
#pragma unroll
    for (int e = 0; e < 16; e++) {
        unsigned col = (e < 8) ? ((cl >> (4 * e)) & 7u) : ((ch >> (4 * (e - 8))) & 7u);
        if (col == (unsigned)n) {
            unsigned row = (e < 8) ? ((rl >> (4 * e)) & 7u) : ((rh >> (4 * (e - 8))) & 7u);
            const float* hr = hsg + row * 16;
#pragma unroll
            for (int c = 0; c < Cout; c += 4) {
                float4 v = *((const float4*)(hr + c));
                acc[c] += v.x; acc[c + 1] += v.y; acc[c + 2] += v.z; acc[c + 3] += v.w;
            }
        }
    }
#pragma unroll
    for (int c = 0; c < Cout; c++)
        hout[c] = fmaxf(fmaf(dis, acc[c], bsh[c]), 0.f);
    __syncthreads();  // protect hs before next layer overwrites it
}

__global__ __launch_bounds__(NTHREADS)
void gnn_kernel(const float* __restrict__ x, const int* __restrict__ ei,
                const float* __restrict__ W1, const float* __restrict__ b1,
                const float* __restrict__ W2, const float* __restrict__ b2,
                const float* __restrict__ W3, const float* __restrict__ b3,
                const float* __restrict__ Wl1, const float* __restrict__ bl1,
                const float* __restrict__ Wl2, const float* __restrict__ bl2,
                float* __restrict__ out, int B)
{
    extern __shared__ float sm[];
    float* Wl1s  = sm;
    float* hsAll = Wl1s + 64 * 132;
    float* zsAll = hsAll + 32 * 132;
    float* Wl2s  = zsAll + 32 * 68;
    float* Wcs   = Wl2s + 16 * 68;
    float* bcs   = Wcs + 176;
    float* bl1s  = bcs + 32;
    float* bl2s  = bl1s + 64;
    int*   esAll = (int*)(bl2s + 16);

    const int tid = threadIdx.x;
    const int gl  = tid >> 3;   // local graph 0..31
    const int n   = tid & 7;    // node 0..7
    const int gg  = blockIdx.x * GPB + gl;
    const bool valid = (gg < B);
    const int gc  = valid ? gg : (B - 1);

    // ---- cooperative weight staging ----
#pragma unroll
    for (int i = 0; i < 8; i++) {
        int idx = tid + i * NTHREADS;        // 0..2047 over 64x32 float4s
        int r = idx >> 5, kk = idx & 31;
        float4 v = ((const float4*)Wl1)[r * 32 + kk];
        *((float4*)(Wl1s + r * 132 + kk * 4)) = v;
    }
    {
        int r = tid >> 4, kk = tid & 15;
        float4 v = ((const float4*)Wl2)[r * 16 + kk];
        *((float4*)(Wl2s + r * 68 + kk * 4)) = v;
    }
    if (tid < 8)   Wcs[tid]       = W1[tid];
    if (tid < 32)  Wcs[8 + tid]   = W2[tid];
    if (tid < 128) Wcs[40 + tid]  = W3[tid];
    if (tid < 4)   bcs[tid]       = b1[tid];
    if (tid < 8)   bcs[4 + tid]   = b2[tid];
    if (tid < 16)  bcs[12 + tid]  = b3[tid];
    if (tid < 64)  bl1s[tid]      = bl1[tid];
    if (tid < 16)  bl2s[tid]      = bl2[tid];

    // ---- per-graph edge + feature loads ----
    int* esg = esAll + gl * 32;
    ((int4*)esg)[n] = ((const int4*)ei)[gc * 8 + n];   // 32 ints/graph, coalesced
    const float2 xv = ((const float2*)x)[gc * 8 + n];  // x[g][n][0:2]

    __syncthreads();

    // pack edges into 4-bit nibbles (node ids are 0..7)
    unsigned rl = 0, rh = 0, cl = 0, ch = 0;
#pragma unroll
    for (int e = 0; e < 8; e++) {
        rl |= ((unsigned)esg[e])      << (4 * e);
        rh |= ((unsigned)esg[8 + e])  << (4 * e);
        cl |= ((unsigned)esg[16 + e]) << (4 * e);
        ch |= ((unsigned)esg[24 + e]) << (4 * e);
    }

    // degree (self-loop included) -> dis = rsqrt(deg)
    int deg = 1;
#pragma unroll
    for (int e = 0; e < 8; e++) {
        deg += (((cl >> (4 * e)) & 7u) == (unsigned)n);
        deg += (((ch >> (4 * e)) & 7u) == (unsigned)n);
    }
    const float dis = rsqrtf((float)deg);

    float* hsg = hsAll + gl * 132;

    // ---- 3 GCN layers ----
    float h0[2] = { xv.x, xv.y };
    float h1[4], h2[8], h3[16];
    gcn_layer<2, 4>(Wcs,      bcs,      h0, h1, hsg, n, dis, rl, rh, cl, ch);
    gcn_layer<4, 8>(Wcs + 8,  bcs + 4,  h1, h2, hsg, n, dis, rl, rh, cl, ch);
    gcn_layer<8, 16>(Wcs + 40, bcs + 12, h2, h3, hsg, n, dis, rl, rh, cl, ch);

    // publish flat[128] = h3 node-major (matches reshape(-1))
#pragma unroll
    for (int c = 0; c < 16; c += 4)
        *((float4*)(hsg + n * 16 + c)) = make_float4(h3[c], h3[c + 1], h3[c + 2], h3[c + 3]);
    __syncthreads();

    // ---- MLP1: z[64] = relu(Wl1 @ flat + bl1); thread n does rows n, n+8, ..., n+56
    float zacc[8];
#pragma unroll
    for (int i = 0; i < 8; i++) zacc[i] = bl1s[n + 8 * i];
    const float4* flat4 = (const float4*)hsg;
#pragma unroll 8
    for (int kk = 0; kk < 32; kk++) {
        float4 f = flat4[kk];
#pragma unroll
        for (int i = 0; i < 8; i++) {
            float4 w = *((const float4*)(Wl1s + (n + 8 * i) * 132 + kk * 4));
            zacc[i] = fmaf(w.x, f.x, zacc[i]);
            zacc[i] = fmaf(w.y, f.y, zacc[i]);
            zacc[i] = fmaf(w.z, f.z, zacc[i]);
            zacc[i] = fmaf(w.w, f.w, zacc[i]);
        }
    }
    float* zsg = zsAll + gl * 68;
#pragma unroll
    for (int i = 0; i < 8; i++) zsg[n + 8 * i] = fmaxf(zacc[i], 0.f);
    __syncthreads();

    // ---- MLP2: out[16] = Wl2 @ z + bl2; thread n does rows 2n, 2n+1
    const float4* z4 = (const float4*)zsg;
    float o0, o1;
#pragma unroll
    for (int r = 0; r < 2; r++) {
        int j = 2 * n + r;
        float a = bl2s[j];
        const float4* w4 = (const float4*)(Wl2s + j * 68);
#pragma unroll
        for (int kk = 0; kk < 16; kk++) {
            float4 zv = z4[kk];
            float4 w  = w4[kk];
            a = fmaf(w.x, zv.x, a);
            a = fmaf(w.y, zv.y, a);
            a = fmaf(w.z, zv.z, a);
            a = fmaf(w.w, zv.w, a);
        }
        if (r == 0) o0 = a; else o1 = a;
    }
    if (valid) ((float2*)out)[gg * 8 + n] = make_float2(o0, o1);
}

extern "C" void kernel_launch(void* const* d_in, const int* in_sizes, int n_in,
                              void* d_out, int out_size)
{
    const float* x   = (const float*)d_in[0];
    const int*   ei  = (const int*)d_in[1];
    const float* W1  = (const float*)d_in[2];
    const float* b1  = (const float*)d_in[3];
    const float* W2  = (const float*)d_in[4];
    const float* b2  = (const float*)d_in[5];
    const float* W3  = (const float*)d_in[6];
    const float* b3  = (const float*)d_in[7];
    const float* Wl1 = (const float*)d_in[8];
    const float* bl1 = (const float*)d_in[9];
    const float* Wl2 = (const float*)d_in[10];
    const float* bl2 = (const float*)d_in[11];
    float* out = (float*)d_out;

    const int B = in_sizes[0] / 16;   // x is [B, 8, 2]
    const int grid = (B + GPB - 1) / GPB;

    cudaFuncSetAttribute(gnn_kernel, cudaFuncAttributeMaxDynamicSharedMemorySize, SMEM_BYTES);
    gnn_kernel<<<grid, NTHREADS, SMEM_BYTES>>>(x, ei, W1, b1, W2, b2, W3, b3,
                                               Wl1, bl1, Wl2, bl2, out, B);
}

// round 3
// speedup vs baseline: 1.8594x; 1.8594x over previous
#include <cuda_runtime.h>

#define NTHREADS 256
#define GPB 128           // graphs per block
#define GPT 4             // graphs per thread

// smem strides (floats)
#define HS_STRIDE 132     // per-graph conv workspace / flat (8 nodes * 16, padded)
#define ZS_STRIDE 68
#define W1S_STRIDE 132

// smem layout (float offsets)
#define SM_HS 0
#define SM_W1 (SM_HS + GPB * HS_STRIDE)          // 16896
#define SM_ZS (SM_W1 + 64 * W1S_STRIDE)          // +8448 = 25344  (ES aliased here)
#define SM_W2 (SM_ZS + GPB * ZS_STRIDE)          // +8704 = 34048
#define SMEM_FLOATS (SM_W2 + 16 * ZS_STRIDE)     // +1088 = 35136
#define SMEM_BYTES (SMEM_FLOATS * 4)             // 140544 B

__constant__ float cW1[8], cb1[4], cW2[32], cb2[8], cW3[128], cb3[16];
__constant__ float cbl1[64], cbl2[16];

typedef unsigned long long u64;

__device__ __forceinline__ u64 fma2(u64 a, u64 b, u64 c) {
    u64 d;
    asm("fma.rn.f32x2 %0, %1, %2, %3;" : "=l"(d) : "l"(a), "l"(b), "l"(c));
    return d;
}
__device__ __forceinline__ u64 pack2(float lo, float hi) {
    u64 d; asm("mov.b64 %0, {%1, %2};" : "=l"(d) : "f"(lo), "f"(hi)); return d;
}
__device__ __forceinline__ float2 unpack2(u64 v) {
    float2 r; asm("mov.b64 {%0, %1}, %2;" : "=f"(r.x), "=f"(r.y) : "l"(v)); return r;
}
// byte (0..255) -> float without I2F
__device__ __forceinline__ float byte2f(unsigned w, int sh) {
    return __uint_as_float(0x4B000000u | ((w >> sh) & 0xFFu)) - 8388608.f;
}

// One GCN layer for GPT graphs per thread (thread = node n of each graph).
template<int Cin, int Cout>
__device__ __forceinline__ void gcn_layer(
    const float* __restrict__ cw, const float* __restrict__ cb,
    float hin[GPT][Cin], float hout[GPT][Cout],
    float* sm, int q, int n,
    const unsigned* c0, const unsigned* c1, const float* dis)
{
    // matmul (weights from constant bank), pre-scale by dis
    float t[GPT][Cout];
#pragma unroll
    for (int c = 0; c < Cout; c++) {
#pragma unroll
        for (int j = 0; j < GPT; j++) {
            float a = 0.f;
#pragma unroll
            for (int k = 0; k < Cin; k++) a = fmaf(cw[c * Cin + k], hin[j][k], a);
            t[j][c] = dis[j] * a;
        }
    }
    // publish scaled features
#pragma unroll
    for (int j = 0; j < GPT; j++) {
        float* hg = sm + SM_HS + (q + 32 * j) * HS_STRIDE + n * 16;
#pragma unroll
        for (int c = 0; c < Cout; c += 4)
            *(float4*)(hg + c) = make_float4(t[j][c], t[j][c + 1], t[j][c + 2], t[j][c + 3]);
    }
    __syncthreads();
    // dense weighted aggregation over 8 neighbors (counts incl. self), packed f32x2
#pragma unroll
    for (int j = 0; j < GPT; j++) {
        u64 acc[Cout / 2];
#pragma unroll
        for (int p = 0; p < Cout / 2; p++) acc[p] = 0ull;
        const float* hg = sm + SM_HS + (q + 32 * j) * HS_STRIDE;
#pragma unroll
        for (int m = 0; m < 8; m++) {
            float cwm = (m < 4) ? byte2f(c0[j], 8 * m) : byte2f(c1[j], 8 * (m - 4));
            u64 cw2 = pack2(cwm, cwm);
            const float* hm = hg + m * 16;
#pragma unroll
            for (int c8 = 0; c8 < Cout; c8 += 4) {
                ulonglong2 v = *(const ulonglong2*)(hm + c8);
                acc[c8 / 2]     = fma2(cw2, v.x, acc[c8 / 2]);
                acc[c8 / 2 + 1] = fma2(cw2, v.y, acc[c8 / 2 + 1]);
            }
        }
#pragma unroll
        for (int p = 0; p < Cout / 2; p++) {
            float2 s = unpack2(acc[p]);
            hout[j][2 * p]     = fmaxf(fmaf(dis[j], s.x, cb[2 * p]),     0.f);
            hout[j][2 * p + 1] = fmaxf(fmaf(dis[j], s.y, cb[2 * p + 1]), 0.f);
        }
    }
    __syncthreads();  // HS reads done before next layer overwrites
}

__global__ __launch_bounds__(NTHREADS, 1)
void gnn_kernel(const float* __restrict__ x, const int* __restrict__ ei,
                const float* __restrict__ Wl1, const float* __restrict__ Wl2,
                float* __restrict__ out, int B)
{
    extern __shared__ float sm[];
    const int tid = threadIdx.x;
    const int q = tid >> 3;       // graph slot 0..31
    const int n = tid & 7;        // node 0..7
    const int gbase = blockIdx.x * GPB;

    // ---- stage edges (coalesced) into ES (aliased over ZS region), stride 36 ints/graph
    int* esI = (int*)(sm + SM_ZS);
#pragma unroll
    for (int i = 0; i < 4; i++) {
        int idx = tid + i * NTHREADS;          // 0..1023
        int lg = idx >> 3, v = idx & 7;
        int g = gbase + lg; if (g >= B) g = B - 1;
        int4 e = ((const int4*)ei)[g * 8 + v];
        *(int4*)(esI + lg * 36 + v * 4) = e;
    }
    // ---- stage Wl1 (row stride 132) and Wl2 (row stride 68)
#pragma unroll
    for (int i = 0; i < 8; i++) {
        int idx = tid + i * NTHREADS;          // 0..2047
        int r = idx >> 5, kk = idx & 31;
        float4 v = ((const float4*)Wl1)[r * 32 + kk];
        *(float4*)(sm + SM_W1 + r * W1S_STRIDE + kk * 4) = v;
    }
    {
        int r = tid >> 4, kk = tid & 15;
        float4 v = ((const float4*)Wl2)[r * 16 + kk];
        *(float4*)(sm + SM_W2 + r * ZS_STRIDE + kk * 4) = v;
    }
    // ---- load x for my 4 graphs
    float h0[GPT][2];
#pragma unroll
    for (int j = 0; j < GPT; j++) {
        int g = gbase + q + 32 * j; if (g >= B) g = B - 1;
        float2 xv = ((const float2*)x)[g * 8 + n];
        h0[j][0] = xv.x; h0[j][1] = xv.y;
    }
    __syncthreads();

    // ---- adjacency byte-counts (self-loop folded in) + degree
    unsigned c0[GPT], c1[GPT]; float dis[GPT];
#pragma unroll
    for (int j = 0; j < GPT; j++) {
        const int4* eg = (const int4*)(esI + (q + 32 * j) * 36);
        unsigned a0 = 0, a1 = 0;
#pragma unroll
        for (int e4 = 0; e4 < 4; e4++) {
            int4 rv = eg[e4];        // rows
            int4 cv = eg[4 + e4];    // cols
            {unsigned inc = (unsigned)(cv.x == n) << (8 * (rv.x & 3)); if (rv.x < 4) a0 += inc; else a1 += inc;}
            {unsigned inc = (unsigned)(cv.y == n) << (8 * (rv.y & 3)); if (rv.y < 4) a0 += inc; else a1 += inc;}
            {unsigned inc = (unsigned)(cv.z == n) << (8 * (rv.z & 3)); if (rv.z < 4) a0 += inc; else a1 += inc;}
            {unsigned inc = (unsigned)(cv.w == n) << (8 * (rv.w & 3)); if (rv.w < 4) a0 += inc; else a1 += inc;}
        }
        if (n < 4) a0 += 1u << (8 * n); else a1 += 1u << (8 * (n - 4));   // self-loop
        unsigned deg = __dp4a(a0, 0x01010101u, __dp4a(a1, 0x01010101u, 0u));
        dis[j] = rsqrtf((float)deg);
        c0[j] = a0; c1[j] = a1;
    }
    __syncthreads();   // done reading ES before ZS reuse later (extra safety)

    // ---- 3 GCN layers
    float h1[GPT][4], h2[GPT][8], h3[GPT][16];
    gcn_layer<2, 4>(cW1, cb1, h0, h1, sm, q, n, c0, c1, dis);
    gcn_layer<4, 8>(cW2, cb2, h1, h2, sm, q, n, c0, c1, dis);
    gcn_layer<8, 16>(cW3, cb3, h2, h3, sm, q, n, c0, c1, dis);

    // ---- publish flat[128] = h3 node-major
#pragma unroll
    for (int j = 0; j < GPT; j++) {
        float* hg = sm + SM_HS + (q + 32 * j) * HS_STRIDE + n * 16;
#pragma unroll
        for (int c = 0; c < 16; c += 4)
            *(float4*)(hg + c) = make_float4(h3[j][c], h3[j][c + 1], h3[j][c + 2], h3[j][c + 3]);
    }
    __syncthreads();

    // ---- MLP1: z[64] = relu(Wl1 @ flat + bl1); thread does rows n+8i for 4 graphs
    u64 acc[8][GPT];
#pragma unroll
    for (int i = 0; i < 8; i++)
#pragma unroll
        for (int j = 0; j < GPT; j++) acc[i][j] = pack2(cbl1[n + 8 * i], 0.f);

#pragma unroll 4
    for (int kk = 0; kk < 32; kk++) {
        u64 f0[GPT], f1[GPT];
#pragma unroll
        for (int j = 0; j < GPT; j++) {
            ulonglong2 fv = *(const ulonglong2*)(sm + SM_HS + (q + 32 * j) * HS_STRIDE + 4 * kk);
            f0[j] = fv.x; f1[j] = fv.y;
        }
#pragma unroll
        for (int i = 0; i < 8; i++) {
            ulonglong2 wv = *(const ulonglong2*)(sm + SM_W1 + (n + 8 * i) * W1S_STRIDE + 4 * kk);
#pragma unroll
            for (int j = 0; j < GPT; j++) {
                acc[i][j] = fma2(wv.x, f0[j], acc[i][j]);
                acc[i][j] = fma2(wv.y, f1[j], acc[i][j]);
            }
        }
    }
#pragma unroll
    for (int j = 0; j < GPT; j++) {
        float* zg = sm + SM_ZS + (q + 32 * j) * ZS_STRIDE;
#pragma unroll
        for (int i = 0; i < 8; i++) {
            float2 s = unpack2(acc[i][j]);
            zg[n + 8 * i] = fmaxf(s.x + s.y, 0.f);
        }
    }
    __syncthreads();

    // ---- MLP2: out[16] = Wl2 @ z + bl2; thread does rows 2n, 2n+1 for 4 graphs
    u64 oa0[GPT], oa1[GPT];
#pragma unroll
    for (int j = 0; j < GPT; j++) {
        oa0[j] = pack2(cbl2[2 * n], 0.f);
        oa1[j] = pack2(cbl2[2 * n + 1], 0.f);
    }
#pragma unroll 4
    for (int kk = 0; kk < 16; kk++) {
        ulonglong2 w0 = *(const ulonglong2*)(sm + SM_W2 + (2 * n)     * ZS_STRIDE + 4 * kk);
        ulonglong2 w1 = *(const ulonglong2*)(sm + SM_W2 + (2 * n + 1) * ZS_STRIDE + 4 * kk);
#pragma unroll
        for (int j = 0; j < GPT; j++) {
            ulonglong2 zv = *(const ulonglong2*)(sm + SM_ZS + (q + 32 * j) * ZS_STRIDE + 4 * kk);
            oa0[j] = fma2(w0.x, zv.x, oa0[j]);
            oa0[j] = fma2(w0.y, zv.y, oa0[j]);
            oa1[j] = fma2(w1.x, zv.x, oa1[j]);
            oa1[j] = fma2(w1.y, zv.y, oa1[j]);
        }
    }
#pragma unroll
    for (int j = 0; j < GPT; j++) {
        int g = gbase + q + 32 * j;
        if (g < B) {
            float2 s0 = unpack2(oa0[j]);
            float2 s1 = unpack2(oa1[j]);
            ((float2*)out)[g * 8 + n] = make_float2(s0.x + s0.y, s1.x + s1.y);
        }
    }
}

extern "C" void kernel_launch(void* const* d_in, const int* in_sizes, int n_in,
                              void* d_out, int out_size)
{
    const float* x   = (const float*)d_in[0];
    const int*   ei  = (const int*)d_in[1];
    float* out = (float*)d_out;

    // small weights / biases -> constant bank (uniform access, off the L1 pipe)
    cudaMemcpyToSymbolAsync(cW1,  d_in[2],   8 * 4, 0, cudaMemcpyDeviceToDevice);
    cudaMemcpyToSymbolAsync(cb1,  d_in[3],   4 * 4, 0, cudaMemcpyDeviceToDevice);
    cudaMemcpyToSymbolAsync(cW2,  d_in[4],  32 * 4, 0, cudaMemcpyDeviceToDevice);
    cudaMemcpyToSymbolAsync(cb2,  d_in[5],   8 * 4, 0, cudaMemcpyDeviceToDevice);
    cudaMemcpyToSymbolAsync(cW3,  d_in[6], 128 * 4, 0, cudaMemcpyDeviceToDevice);
    cudaMemcpyToSymbolAsync(cb3,  d_in[7],  16 * 4, 0, cudaMemcpyDeviceToDevice);
    cudaMemcpyToSymbolAsync(cbl1, d_in[9],  64 * 4, 0, cudaMemcpyDeviceToDevice);
    cudaMemcpyToSymbolAsync(cbl2, d_in[11], 16 * 4, 0, cudaMemcpyDeviceToDevice);

    const int B = in_sizes[0] / 16;   // x is [B, 8, 2]
    const int grid = (B + GPB - 1) / GPB;

    cudaFuncSetAttribute(gnn_kernel, cudaFuncAttributeMaxDynamicSharedMemorySize, SMEM_BYTES);
    gnn_kernel<<<grid, NTHREADS, SMEM_BYTES>>>(x, ei, (const float*)d_in[8],
                                               (const float*)d_in[10], out, B);
}

// round 4
// speedup vs baseline: 2.1369x; 1.1493x over previous
#include <cuda_runtime.h>

#define NTHREADS 256
#define GPB 128           // graphs per block
#define GPT 4             // graphs per thread (conv phase)

#define SLOT_STRIDE 132   // floats per graph slot (HS) and per W1 row
#define W2_STRIDE 68

// smem layout (float offsets). Edges and z alias the HS region (time-sliced).
#define SM_HS 0
#define SM_W1 (GPB * SLOT_STRIDE)                // 16896
#define SM_W2 (SM_W1 + 64 * SLOT_STRIDE)         // 25344
#define SMEM_FLOATS (SM_W2 + 16 * W2_STRIDE)     // 26432
#define SMEM_BYTES (SMEM_FLOATS * 4)             // 105728 B -> 2 blocks/SM

__constant__ float cW1[8], cb1[4], cW2[32], cb2[8], cW3[128], cb3[16];
__constant__ float cbl1[64], cbl2[16];

typedef unsigned long long u64;

__device__ __forceinline__ u64 fma2(u64 a, u64 b, u64 c) {
    u64 d;
    asm("fma.rn.f32x2 %0, %1, %2, %3;" : "=l"(d) : "l"(a), "l"(b), "l"(c));
    return d;
}
__device__ __forceinline__ u64 pack2(float lo, float hi) {
    u64 d; asm("mov.b64 %0, {%1, %2};" : "=l"(d) : "f"(lo), "f"(hi)); return d;
}
__device__ __forceinline__ float2 unpack2(u64 v) {
    float2 r; asm("mov.b64 {%0, %1}, %2;" : "=f"(r.x), "=f"(r.y) : "l"(v)); return r;
}
// byte (0..255) -> float without I2F
__device__ __forceinline__ float byte2f(unsigned wd, int sh) {
    return __uint_as_float(0x4B000000u | ((wd >> sh) & 0xFFu)) - 8388608.f;
}

// GCN layer, aggregate-FIRST (A@X)@W^T form. Thread = node n of GPT graphs.
template<int Cin, int Cout>
__device__ __forceinline__ void gcn_layer(
    const float* __restrict__ cw, const float* __restrict__ cb,
    float hin[GPT][Cin], float hout[GPT][Cout],
    float* sm, int q, int n,
    const unsigned* c0, const unsigned* c1, const float* dis)
{
    // publish dis-scaled inputs (node stride 16 floats)
#pragma unroll
    for (int j = 0; j < GPT; j++) {
        float* hg = sm + SM_HS + (q + 32 * j) * SLOT_STRIDE + n * 16;
        if (Cin == 2) {
            *(float2*)hg = make_float2(hin[j][0] * dis[j], hin[j][1] * dis[j]);
        } else {
#pragma unroll
            for (int k = 0; k < Cin; k += 4)
                *(float4*)(hg + k) = make_float4(hin[j][k] * dis[j], hin[j][k+1] * dis[j],
                                                 hin[j][k+2] * dis[j], hin[j][k+3] * dis[j]);
        }
    }
    __syncthreads();
    // aggregate Cin channels with byte-count weights, then matmul to Cout
#pragma unroll
    for (int j = 0; j < GPT; j++) {
        u64 agg[(Cin + 1) / 2];
#pragma unroll
        for (int p = 0; p < (Cin + 1) / 2; p++) agg[p] = 0ull;
        const float* hg = sm + SM_HS + (q + 32 * j) * SLOT_STRIDE;
#pragma unroll
        for (int m = 0; m < 8; m++) {
            float cwm = (m < 4) ? byte2f(c0[j], 8 * m) : byte2f(c1[j], 8 * (m - 4));
            u64 cw2 = pack2(cwm, cwm);
            const float* hm = hg + m * 16;
            if (Cin == 2) {
                agg[0] = fma2(cw2, *(const u64*)hm, agg[0]);
            } else {
#pragma unroll
                for (int k = 0; k < Cin; k += 4) {
                    ulonglong2 v = *(const ulonglong2*)(hm + k);
                    agg[k / 2]     = fma2(cw2, v.x, agg[k / 2]);
                    agg[k / 2 + 1] = fma2(cw2, v.y, agg[k / 2 + 1]);
                }
            }
        }
        float a[Cin];
#pragma unroll
        for (int p = 0; p < Cin / 2; p++) {
            float2 s = unpack2(agg[p]);
            a[2 * p] = s.x; a[2 * p + 1] = s.y;
        }
#pragma unroll
        for (int c = 0; c < Cout; c++) {
            float t = 0.f;
#pragma unroll
            for (int k = 0; k < Cin; k++) t = fmaf(cw[c * Cin + k], a[k], t);
            hout[j][c] = fmaxf(fmaf(dis[j], t, cb[c]), 0.f);
        }
    }
    __syncthreads();   // all reads done before region is overwritten
}

__global__ __launch_bounds__(NTHREADS, 2)
void gnn_kernel(const float* __restrict__ x, const int* __restrict__ ei,
                const float* __restrict__ Wl1, const float* __restrict__ Wl2,
                float* __restrict__ out, int B)
{
    extern __shared__ float sm[];
    const int tid  = threadIdx.x;
    const int q    = tid >> 3;    // graph slot 0..31
    const int n    = tid & 7;     // node 0..7
    const int lane = tid & 31;
    const int w    = tid >> 5;    // warp 0..7
    const int gbase = blockIdx.x * GPB;

    // ---- stage edges into HS alias (slot stride 132 ints)
    int* esI = (int*)sm;
#pragma unroll
    for (int i = 0; i < 4; i++) {
        int idx = tid + i * NTHREADS;          // 0..1023
        int lg = idx >> 3, v = idx & 7;
        int g = gbase + lg; if (g >= B) g = B - 1;
        int4 e = ((const int4*)ei)[g * 8 + v];
        *(int4*)(esI + lg * SLOT_STRIDE + v * 4) = e;
    }
    // ---- stage Wl1 with PERMUTED rows: row r -> slot (r&1)*32 + (r>>1)
#pragma unroll
    for (int i = 0; i < 8; i++) {
        int idx = tid + i * NTHREADS;          // 0..2047
        int r = idx >> 5, kk = idx & 31;
        int slot = (r & 1) * 32 + (r >> 1);
        float4 v = ((const float4*)Wl1)[r * 32 + kk];
        *(float4*)(sm + SM_W1 + slot * SLOT_STRIDE + kk * 4) = v;
    }
    {
        int r = tid >> 4, kk = tid & 15;
        float4 v = ((const float4*)Wl2)[r * 16 + kk];
        *(float4*)(sm + SM_W2 + r * W2_STRIDE + kk * 4) = v;
    }
    // ---- load x for my GPT graphs
    float h0[GPT][2];
#pragma unroll
    for (int j = 0; j < GPT; j++) {
        int g = gbase + q + 32 * j; if (g >= B) g = B - 1;
        float2 xv = ((const float2*)x)[g * 8 + n];
        h0[j][0] = xv.x; h0[j][1] = xv.y;
    }
    __syncthreads();

    // ---- adjacency byte-counts (self-loop folded in) + degree
    unsigned c0[GPT], c1[GPT]; float dis[GPT];
#pragma unroll
    for (int j = 0; j < GPT; j++) {
        const int4* eg = (const int4*)(esI + (q + 32 * j) * SLOT_STRIDE);
        unsigned a0 = 0, a1 = 0;
#pragma unroll
        for (int e4 = 0; e4 < 4; e4++) {
            int4 rv = eg[e4];        // rows
            int4 cv = eg[4 + e4];    // cols
            {unsigned inc = (unsigned)(cv.x == n) << (8 * (rv.x & 3)); if (rv.x < 4) a0 += inc; else a1 += inc;}
            {unsigned inc = (unsigned)(cv.y == n) << (8 * (rv.y & 3)); if (rv.y < 4) a0 += inc; else a1 += inc;}
            {unsigned inc = (unsigned)(cv.z == n) << (8 * (rv.z & 3)); if (rv.z < 4) a0 += inc; else a1 += inc;}
            {unsigned inc = (unsigned)(cv.w == n) << (8 * (rv.w & 3)); if (rv.w < 4) a0 += inc; else a1 += inc;}
        }
        if (n < 4) a0 += 1u << (8 * n); else a1 += 1u << (8 * (n - 4));
        unsigned deg = __dp4a(a0, 0x01010101u, __dp4a(a1, 0x01010101u, 0u));
        dis[j] = rsqrtf((float)deg);
        c0[j] = a0; c1[j] = a1;
    }
    __syncthreads();   // ES fully consumed before layer1 publish overwrites it

    // ---- 3 GCN layers (aggregate-first)
    float h1[GPT][4], h2[GPT][8], h3[GPT][16];
    gcn_layer<2, 4>(cW1, cb1, h0, h1, sm, q, n, c0, c1, dis);
    gcn_layer<4, 8>(cW2, cb2, h1, h2, sm, q, n, c0, c1, dis);
    gcn_layer<8, 16>(cW3, cb3, h2, h3, sm, q, n, c0, c1, dis);

    // ---- publish flat[128] = h3 node-major
#pragma unroll
    for (int j = 0; j < GPT; j++) {
        float* hg = sm + SM_HS + (q + 32 * j) * SLOT_STRIDE + n * 16;
#pragma unroll
        for (int c = 0; c < 16; c += 4)
            *(float4*)(hg + c) = make_float4(h3[j][c], h3[j][c+1], h3[j][c+2], h3[j][c+3]);
    }
    __syncthreads();

    // ======== MLP1 (warp-cooperative): lane computes z rows {2l, 2l+1}
    // for the 16 graphs its warp owns: gi=0..15 -> slot 4w+(gi&3)+32*(gi>>2)
    float* wbase = sm + SM_HS + (4 * w) * SLOT_STRIDE;   // warp's slot-group base
#define GOFF(gi) ((((gi) & 3) + 32 * ((gi) >> 2)) * SLOT_STRIDE)

    u64 accA[16], accB[16];
    {
        u64 bA = pack2(cbl1[2 * lane], 0.f);
        u64 bB = pack2(cbl1[2 * lane + 1], 0.f);
#pragma unroll
        for (int gi = 0; gi < 16; gi++) { accA[gi] = bA; accB[gi] = bB; }
    }
    const float* w1a = sm + SM_W1 + lane * SLOT_STRIDE;        // row 2l (slot l)
    const float* w1b = sm + SM_W1 + (32 + lane) * SLOT_STRIDE; // row 2l+1
#pragma unroll 2
    for (int kk = 0; kk < 32; kk++) {
        ulonglong2 wa = *(const ulonglong2*)(w1a + 4 * kk);
        ulonglong2 wb = *(const ulonglong2*)(w1b + 4 * kk);
#pragma unroll
        for (int gi = 0; gi < 16; gi++) {
            ulonglong2 f = *(const ulonglong2*)(wbase + GOFF(gi) + 4 * kk);
            accA[gi] = fma2(wa.x, f.x, accA[gi]);
            accA[gi] = fma2(wa.y, f.y, accA[gi]);
            accB[gi] = fma2(wb.x, f.x, accB[gi]);
            accB[gi] = fma2(wb.y, f.y, accB[gi]);
        }
    }
    __syncthreads();   // flat fully consumed -> safe to overwrite with z
#pragma unroll
    for (int gi = 0; gi < 16; gi++) {
        float2 sA = unpack2(accA[gi]);
        float2 sB = unpack2(accB[gi]);
        *(float2*)(wbase + GOFF(gi) + 2 * lane) =
            make_float2(fmaxf(sA.x + sA.y, 0.f), fmaxf(sB.x + sB.y, 0.f));
    }
    __syncthreads();

    // ======== MLP2: lane = (h = l>>4, r = l&15); row r for 8 graphs p=0..7
    const int r16 = lane & 15, hh = lane >> 4;
    const float* zb = sm + SM_HS + (4 * w) * SLOT_STRIDE + hh * (2 * 32 * SLOT_STRIDE);
#define ZOFF(p) ((((p) & 3) + 32 * ((p) >> 2)) * SLOT_STRIDE)
    u64 oacc[8];
    {
        u64 bO = pack2(cbl2[r16], 0.f);
#pragma unroll
        for (int p = 0; p < 8; p++) oacc[p] = bO;
    }
    const float* w2r = sm + SM_W2 + r16 * W2_STRIDE;
#pragma unroll 4
    for (int kk = 0; kk < 16; kk++) {
        ulonglong2 wv = *(const ulonglong2*)(w2r + 4 * kk);
#pragma unroll
        for (int p = 0; p < 8; p++) {
            ulonglong2 zv = *(const ulonglong2*)(zb + ZOFF(p) + 4 * kk);
            oacc[p] = fma2(wv.x, zv.x, oacc[p]);
            oacc[p] = fma2(wv.y, zv.y, oacc[p]);
        }
    }
#pragma unroll
    for (int p = 0; p < 8; p++) {
        int g = gbase + 4 * w + (p & 3) + 32 * (2 * hh + (p >> 2));
        if (g < B) {
            float2 s = unpack2(oacc[p]);
            out[g * 16 + r16] = s.x + s.y;
        }
    }
}

extern "C" void kernel_launch(void* const* d_in, const int* in_sizes, int n_in,
                              void* d_out, int out_size)
{
    const float* x  = (const float*)d_in[0];
    const int*   ei = (const int*)d_in[1];
    float* out = (float*)d_out;

    cudaMemcpyToSymbolAsync(cW1,  d_in[2],   8 * 4, 0, cudaMemcpyDeviceToDevice);
    cudaMemcpyToSymbolAsync(cb1,  d_in[3],   4 * 4, 0, cudaMemcpyDeviceToDevice);
    cudaMemcpyToSymbolAsync(cW2,  d_in[4],  32 * 4, 0, cudaMemcpyDeviceToDevice);
    cudaMemcpyToSymbolAsync(cb2,  d_in[5],   8 * 4, 0, cudaMemcpyDeviceToDevice);
    cudaMemcpyToSymbolAsync(cW3,  d_in[6], 128 * 4, 0, cudaMemcpyDeviceToDevice);
    cudaMemcpyToSymbolAsync(cb3,  d_in[7],  16 * 4, 0, cudaMemcpyDeviceToDevice);
    cudaMemcpyToSymbolAsync(cbl1, d_in[9],  64 * 4, 0, cudaMemcpyDeviceToDevice);
    cudaMemcpyToSymbolAsync(cbl2, d_in[11], 16 * 4, 0, cudaMemcpyDeviceToDevice);

    const int B = in_sizes[0] / 16;   // x is [B, 8, 2]
    const int grid = (B + GPB - 1) / GPB;

    cudaFuncSetAttribute(gnn_kernel, cudaFuncAttributeMaxDynamicSharedMemorySize, SMEM_BYTES);
    gnn_kernel<<<grid, NTHREADS, SMEM_BYTES>>>(x, ei, (const float*)d_in[8],
                                               (const float*)d_in[10], out, B);
}

// round 6
// speedup vs baseline: 3.4984x; 1.6371x over previous
#include <cuda_runtime.h>

#define NTHREADS 256
#define GPB 128           // graphs per block
#define GPT 4             // graphs per thread (conv phase)

#define SLOT_STRIDE 132   // floats per graph slot (HS) and per W1 row
#define W2_STRIDE 68

// smem layout (float offsets). Edges and z alias the HS region (time-sliced).
#define SM_HS 0
#define SM_W1 (GPB * SLOT_STRIDE)                // 16896
#define SM_W2 (SM_W1 + 64 * SLOT_STRIDE)         // 25344
#define SMEM_FLOATS (SM_W2 + 16 * W2_STRIDE)     // 26432
#define SMEM_BYTES (SMEM_FLOATS * 4)             // 105728 B -> 2 blocks/SM

__constant__ float cW1[8], cb1[4], cW2[32], cb2[8], cW3[128], cb3[16];
__constant__ float cbl1[64], cbl2[16];

typedef unsigned long long u64;

__device__ __forceinline__ u64 fma2(u64 a, u64 b, u64 c) {
    u64 d;
    asm("fma.rn.f32x2 %0, %1, %2, %3;" : "=l"(d) : "l"(a), "l"(b), "l"(c));
    return d;
}
__device__ __forceinline__ u64 pack2(float lo, float hi) {
    u64 d; asm("mov.b64 %0, {%1, %2};" : "=l"(d) : "f"(lo), "f"(hi)); return d;
}
__device__ __forceinline__ float2 unpack2(u64 v) {
    float2 r; asm("mov.b64 {%0, %1}, %2;" : "=f"(r.x), "=f"(r.y) : "l"(v)); return r;
}
// byte (0..255) -> float without I2F
__device__ __forceinline__ float byte2f(unsigned wd, int sh) {
    return __uint_as_float(0x4B000000u | ((wd >> sh) & 0xFFu)) - 8388608.f;
}
__device__ __forceinline__ float tf32f(float f) {
    unsigned u; asm("cvt.rna.tf32.f32 %0, %1;" : "=r"(u) : "f"(f));
    return __uint_as_float(u);
}
// D += A(16x8,row) * B(8x8,col);  tf32 operands, fp32 accumulate
__device__ __forceinline__ void mma_tf32(float d[4],
    unsigned a0, unsigned a1, unsigned a2, unsigned a3,
    unsigned b0, unsigned b1)
{
    asm("mma.sync.aligned.m16n8k8.row.col.f32.tf32.tf32.f32 "
        "{%0,%1,%2,%3}, {%4,%5,%6,%7}, {%8,%9}, {%0,%1,%2,%3};"
        : "+f"(d[0]), "+f"(d[1]), "+f"(d[2]), "+f"(d[3])
        : "r"(a0), "r"(a1), "r"(a2), "r"(a3), "r"(b0), "r"(b1));
}

// GCN layer, aggregate-FIRST (A@X)@W^T form. Thread = node n of GPT graphs.
template<int Cin, int Cout>
__device__ __forceinline__ void gcn_layer(
    const float* __restrict__ cw, const float* __restrict__ cb,
    float hin[GPT][Cin], float hout[GPT][Cout],
    float* sm, int q, int n,
    const unsigned* c0, const unsigned* c1, const float* dis)
{
    // publish dis-scaled inputs (node stride 16 floats)
#pragma unroll
    for (int j = 0; j < GPT; j++) {
        float* hg = sm + SM_HS + (q + 32 * j) * SLOT_STRIDE + n * 16;
        if (Cin == 2) {
            *(float2*)hg = make_float2(hin[j][0] * dis[j], hin[j][1] * dis[j]);
        } else {
#pragma unroll
            for (int k = 0; k < Cin; k += 4)
                *(float4*)(hg + k) = make_float4(hin[j][k] * dis[j], hin[j][k+1] * dis[j],
                                                 hin[j][k+2] * dis[j], hin[j][k+3] * dis[j]);
        }
    }
    __syncthreads();
    // aggregate Cin channels with byte-count weights, then matmul to Cout
#pragma unroll
    for (int j = 0; j < GPT; j++) {
        u64 agg[(Cin + 1) / 2];
#pragma unroll
        for (int p = 0; p < (Cin + 1) / 2; p++) agg[p] = 0ull;
        const float* hg = sm + SM_HS + (q + 32 * j) * SLOT_STRIDE;
#pragma unroll
        for (int m = 0; m < 8; m++) {
            float cwm = (m < 4) ? byte2f(c0[j], 8 * m) : byte2f(c1[j], 8 * (m - 4));
            u64 cw2 = pack2(cwm, cwm);
            const float* hm = hg + m * 16;
            if (Cin == 2) {
                agg[0] = fma2(cw2, *(const u64*)hm, agg[0]);
            } else {
#pragma unroll
                for (int k = 0; k < Cin; k += 4) {
                    ulonglong2 v = *(const ulonglong2*)(hm + k);
                    agg[k / 2]     = fma2(cw2, v.x, agg[k / 2]);
                    agg[k / 2 + 1] = fma2(cw2, v.y, agg[k / 2 + 1]);
                }
            }
        }
        float a[Cin];
#pragma unroll
        for (int p = 0; p < Cin / 2; p++) {
            float2 s = unpack2(agg[p]);
            a[2 * p] = s.x; a[2 * p + 1] = s.y;
        }
#pragma unroll
        for (int c = 0; c < Cout; c++) {
            float t = 0.f;
#pragma unroll
            for (int k = 0; k < Cin; k++) t = fmaf(cw[c * Cin + k], a[k], t);
            hout[j][c] = fmaxf(fmaf(dis[j], t, cb[c]), 0.f);
        }
    }
    __syncthreads();   // all reads done before region is overwritten
}

__global__ __launch_bounds__(NTHREADS, 2)
void gnn_kernel(const float* __restrict__ x, const int* __restrict__ ei,
                const float* __restrict__ Wl1, const float* __restrict__ Wl2,
                float* __restrict__ out, int B)
{
    extern __shared__ float sm[];
    const int tid  = threadIdx.x;
    const int q    = tid >> 3;    // graph slot 0..31 (conv phase)
    const int n    = tid & 7;     // node 0..7
    const int lane = tid & 31;
    const int w    = tid >> 5;    // warp 0..7
    const int gbase = blockIdx.x * GPB;

    // ---- stage edges into HS alias (slot stride 132 ints)
    int* esI = (int*)sm;
#pragma unroll
    for (int i = 0; i < 4; i++) {
        int idx = tid + i * NTHREADS;          // 0..1023
        int lg = idx >> 3, v = idx & 7;
        int g = gbase + lg; if (g >= B) g = B - 1;
        int4 e = ((const int4*)ei)[g * 8 + v];
        *(int4*)(esI + lg * SLOT_STRIDE + v * 4) = e;
    }
    // ---- stage Wl1 rows (tf32-truncated), row r at slot r, stride 132
#pragma unroll
    for (int i = 0; i < 8; i++) {
        int idx = tid + i * NTHREADS;          // 0..2047
        int r = idx >> 5, kk = idx & 31;
        float4 v = ((const float4*)Wl1)[r * 32 + kk];
        v.x = tf32f(v.x); v.y = tf32f(v.y); v.z = tf32f(v.z); v.w = tf32f(v.w);
        *(float4*)(sm + SM_W1 + r * SLOT_STRIDE + kk * 4) = v;
    }
    {
        int r = tid >> 4, kk = tid & 15;
        float4 v = ((const float4*)Wl2)[r * 16 + kk];
        v.x = tf32f(v.x); v.y = tf32f(v.y); v.z = tf32f(v.z); v.w = tf32f(v.w);
        *(float4*)(sm + SM_W2 + r * W2_STRIDE + kk * 4) = v;
    }
    // ---- load x for my GPT graphs
    float h0[GPT][2];
#pragma unroll
    for (int j = 0; j < GPT; j++) {
        int g = gbase + q + 32 * j; if (g >= B) g = B - 1;
        float2 xv = ((const float2*)x)[g * 8 + n];
        h0[j][0] = xv.x; h0[j][1] = xv.y;
    }
    __syncthreads();

    // ---- adjacency byte-counts (self-loop folded in) + degree
    unsigned c0[GPT], c1[GPT]; float dis[GPT];
#pragma unroll
    for (int j = 0; j < GPT; j++) {
        const int4* eg = (const int4*)(esI + (q + 32 * j) * SLOT_STRIDE);
        unsigned a0 = 0, a1 = 0;
#pragma unroll
        for (int e4 = 0; e4 < 4; e4++) {
            int4 rv = eg[e4];        // rows
            int4 cv = eg[4 + e4];    // cols
            {unsigned inc = (unsigned)(cv.x == n) << (8 * (rv.x & 3)); if (rv.x < 4) a0 += inc; else a1 += inc;}
            {unsigned inc = (unsigned)(cv.y == n) << (8 * (rv.y & 3)); if (rv.y < 4) a0 += inc; else a1 += inc;}
            {unsigned inc = (unsigned)(cv.z == n) << (8 * (rv.z & 3)); if (rv.z < 4) a0 += inc; else a1 += inc;}
            {unsigned inc = (unsigned)(cv.w == n) << (8 * (rv.w & 3)); if (rv.w < 4) a0 += inc; else a1 += inc;}
        }
        if (n < 4) a0 += 1u << (8 * n); else a1 += 1u << (8 * (n - 4));
        unsigned deg = __dp4a(a0, 0x01010101u, __dp4a(a1, 0x01010101u, 0u));
        dis[j] = rsqrtf((float)deg);
        c0[j] = a0; c1[j] = a1;
    }
    __syncthreads();   // ES fully consumed before layer1 publish overwrites it

    // ---- 3 GCN layers (aggregate-first)
    float h1[GPT][4], h2[GPT][8], h3[GPT][16];
    gcn_layer<2, 4>(cW1, cb1, h0, h1, sm, q, n, c0, c1, dis);
    gcn_layer<4, 8>(cW2, cb2, h1, h2, sm, q, n, c0, c1, dis);
    gcn_layer<8, 16>(cW3, cb3, h2, h3, sm, q, n, c0, c1, dis);

    // ---- publish flat[128] = h3 node-major, PRE-TRUNCATED to tf32 for the mma
#pragma unroll
    for (int j = 0; j < GPT; j++) {
        float* hg = sm + SM_HS + (q + 32 * j) * SLOT_STRIDE + n * 16;
#pragma unroll
        for (int c = 0; c < 16; c += 4)
            *(float4*)(hg + c) = make_float4(tf32f(h3[j][c]), tf32f(h3[j][c+1]),
                                             tf32f(h3[j][c+2]), tf32f(h3[j][c+3]));
    }
    __syncthreads();

    // ======== MLP1 via tf32 mma: warp w owns graphs at slots [16w, 16w+16)
    // A = flat[16 x 128] (row g = slot 16w+g), B = Wl1 (row-major = col-major k x n)
    const int grp = lane >> 2;    // 0..7
    const int qd  = lane & 3;     // 0..3
    const float* a0p = sm + SM_HS + (16 * w + grp) * SLOT_STRIDE + qd;  // row grp
    const float* a1p = a0p + 8 * SLOT_STRIDE;                            // row grp+8
    const float* bP  = sm + SM_W1 + grp * SLOT_STRIDE + qd;              // + nt*8*stride + kc*8

    float d[8][4];
#pragma unroll
    for (int nt = 0; nt < 8; nt++) {
        float cc0 = cbl1[nt * 8 + 2 * qd], cc1 = cbl1[nt * 8 + 2 * qd + 1];
        d[nt][0] = cc0; d[nt][1] = cc1; d[nt][2] = cc0; d[nt][3] = cc1;
    }
#pragma unroll
    for (int kc = 0; kc < 16; kc++) {
        unsigned a0 = __float_as_uint(a0p[kc * 8]);
        unsigned a1 = __float_as_uint(a1p[kc * 8]);
        unsigned a2 = __float_as_uint(a0p[kc * 8 + 4]);
        unsigned a3 = __float_as_uint(a1p[kc * 8 + 4]);
#pragma unroll
        for (int nt = 0; nt < 8; nt++) {
            unsigned b0 = __float_as_uint(bP[nt * 8 * SLOT_STRIDE + kc * 8]);
            unsigned b1 = __float_as_uint(bP[nt * 8 * SLOT_STRIDE + kc * 8 + 4]);
            mma_tf32(d[nt], a0, a1, a2, a3, b0, b1);
        }
    }
    // relu + tf32-truncate + store z into own slots (words 0..63)
    float* z0 = sm + SM_HS + (16 * w + grp) * SLOT_STRIDE;
    float* z1 = z0 + 8 * SLOT_STRIDE;
#pragma unroll
    for (int nt = 0; nt < 8; nt++) {
        *(float2*)(z0 + nt * 8 + 2 * qd) =
            make_float2(tf32f(fmaxf(d[nt][0], 0.f)), tf32f(fmaxf(d[nt][1], 0.f)));
        *(float2*)(z1 + nt * 8 + 2 * qd) =
            make_float2(tf32f(fmaxf(d[nt][2], 0.f)), tf32f(fmaxf(d[nt][3], 0.f)));
    }
    __syncwarp();

    // ======== MLP2 via tf32 mma: A = Z[16 x 64], B = Wl2 (16 rows x 64)
    float e[2][4];
#pragma unroll
    for (int nt = 0; nt < 2; nt++) {
        float cc0 = cbl2[nt * 8 + 2 * qd], cc1 = cbl2[nt * 8 + 2 * qd + 1];
        e[nt][0] = cc0; e[nt][1] = cc1; e[nt][2] = cc0; e[nt][3] = cc1;
    }
    const float* b2P = sm + SM_W2 + grp * W2_STRIDE + qd;
#pragma unroll
    for (int kc = 0; kc < 8; kc++) {
        unsigned a0 = __float_as_uint(z0[kc * 8 + qd]);        // FIX: +qd lane offset
        unsigned a1 = __float_as_uint(z1[kc * 8 + qd]);
        unsigned a2 = __float_as_uint(z0[kc * 8 + qd + 4]);
        unsigned a3 = __float_as_uint(z1[kc * 8 + qd + 4]);
#pragma unroll
        for (int nt = 0; nt < 2; nt++) {
            unsigned b0 = __float_as_uint(b2P[nt * 8 * W2_STRIDE + kc * 8]);
            unsigned b1 = __float_as_uint(b2P[nt * 8 * W2_STRIDE + kc * 8 + 4]);
            mma_tf32(e[nt], a0, a1, a2, a3, b0, b1);
        }
    }
    // D fragments straight to gmem: lane holds out[g0][c], out[g0][c+1], out[g0+8][c], [c+1]
    const int g0 = gbase + 16 * w + grp;
#pragma unroll
    for (int nt = 0; nt < 2; nt++) {
        int col = nt * 8 + 2 * qd;
        if (g0 < B)
            *(float2*)(out + g0 * 16 + col) = make_float2(e[nt][0], e[nt][1]);
        if (g0 + 8 < B)
            *(float2*)(out + (g0 + 8) * 16 + col) = make_float2(e[nt][2], e[nt][3]);
    }
}

extern "C" void kernel_launch(void* const* d_in, const int* in_sizes, int n_in,
                              void* d_out, int out_size)
{
    const float* x  = (const float*)d_in[0];
    const int*   ei = (const int*)d_in[1];
    float* out = (float*)d_out;

    cudaMemcpyToSymbolAsync(cW1,  d_in[2],   8 * 4, 0, cudaMemcpyDeviceToDevice);
    cudaMemcpyToSymbolAsync(cb1,  d_in[3],   4 * 4, 0, cudaMemcpyDeviceToDevice);
    cudaMemcpyToSymbolAsync(cW2,  d_in[4],  32 * 4, 0, cudaMemcpyDeviceToDevice);
    cudaMemcpyToSymbolAsync(cb2,  d_in[5],   8 * 4, 0, cudaMemcpyDeviceToDevice);
    cudaMemcpyToSymbolAsync(cW3,  d_in[6], 128 * 4, 0, cudaMemcpyDeviceToDevice);
    cudaMemcpyToSymbolAsync(cb3,  d_in[7],  16 * 4, 0, cudaMemcpyDeviceToDevice);
    cudaMemcpyToSymbolAsync(cbl1, d_in[9],  64 * 4, 0, cudaMemcpyDeviceToDevice);
    cudaMemcpyToSymbolAsync(cbl2, d_in[11], 16 * 4, 0, cudaMemcpyDeviceToDevice);

    const int B = in_sizes[0] / 16;   // x is [B, 8, 2]
    const int grid = (B + GPB - 1) / GPB;

    cudaFuncSetAttribute(gnn_kernel, cudaFuncAttributeMaxDynamicSharedMemorySize, SMEM_BYTES);
    gnn_kernel<<<grid, NTHREADS, SMEM_BYTES>>>(x, ei, (const float*)d_in[8],
                                               (const float*)d_in[10], out, B);
}

// round 7
// speedup vs baseline: 4.7570x; 1.3598x over previous
#include <cuda_runtime.h>
#include <cuda_fp16.h>

#define NTHREADS 256
#define GPB 128           // graphs per block
#define GPT 4             // graphs per thread (conv phase)

#define SLOT_W 68         // 32-bit words per graph slot (128 halfs + pad); 68%32=4 -> conflict-free
#define W1_W 68           // words per Wl1 row (128 halfs + pad)
#define W2_W 36           // words per Wl2 row (64 halfs + pad); 36%32=4

// smem layout in 32-bit words. Edges + conv features + flat + z all live in HS slots.
#define SM_HS 0
#define SM_W1 (GPB * SLOT_W)              // 8704
#define SM_W2 (SM_W1 + 64 * W1_W)         // 13056
#define SMEM_WORDS (SM_W2 + 16 * W2_W)    // 13632
#define SMEM_BYTES (SMEM_WORDS * 4)       // 54528 B -> 3 blocks/SM

__constant__ float cW1[8], cb1[4], cW2[32], cb2[8], cW3[128], cb3[16];
__constant__ float cbl1[64], cbl2[16];

__device__ __forceinline__ __half2 u2h2(unsigned u) { return *(__half2*)&u; }
__device__ __forceinline__ unsigned h22u(__half2 h) { return *(unsigned*)&h; }

// count byte (0..16) -> broadcast half2
__device__ __forceinline__ __half2 cnt2(unsigned wd, int m) {
    unsigned b = (wd >> (8 * m)) & 0xFFu;
    return __half2half2(__ushort2half_rn((unsigned short)b));
}

// fp16 mma: D(16x8,f32) += A(16x16,f16) * B(16x8,f16)
__device__ __forceinline__ void mma_f16(float d[4],
    unsigned a0, unsigned a1, unsigned a2, unsigned a3,
    unsigned b0, unsigned b1)
{
    asm("mma.sync.aligned.m16n8k16.row.col.f32.f16.f16.f32 "
        "{%0,%1,%2,%3}, {%4,%5,%6,%7}, {%8,%9}, {%0,%1,%2,%3};"
        : "+f"(d[0]), "+f"(d[1]), "+f"(d[2]), "+f"(d[3])
        : "r"(a0), "r"(a1), "r"(a2), "r"(a3), "r"(b0), "r"(b1));
}

__global__ __launch_bounds__(NTHREADS, 3)
void gnn_kernel(const float* __restrict__ x, const int* __restrict__ ei,
                const float* __restrict__ Wl1, const float* __restrict__ Wl2,
                float* __restrict__ out, int B)
{
    extern __shared__ float smf[];
    unsigned* smw = (unsigned*)smf;

    const int tid  = threadIdx.x;
    const int q    = tid >> 3;     // slot 0..31 (conv phase; +32j for graph j)
    const int n    = tid & 7;      // node 0..7
    const int lane = tid & 31;
    const int w    = tid >> 5;     // warp 0..7
    const int gbase = blockIdx.x * GPB;

    // ---- stage Wl1/Wl2 as fp16 (block-cooperative; consumed only after the ONE barrier)
#pragma unroll
    for (int i = 0; i < 8; i++) {
        int idx = tid + i * NTHREADS;           // 0..2047 float4s of Wl1 (64x128)
        int r = idx >> 5, kk = idx & 31;
        float4 v = ((const float4*)Wl1)[r * 32 + kk];
        uint2 p;
        p.x = h22u(__floats2half2_rn(v.x, v.y));
        p.y = h22u(__floats2half2_rn(v.z, v.w));
        *(uint2*)(smw + SM_W1 + r * W1_W + 2 * kk) = p;
    }
    {
        int r = tid >> 4, kk = tid & 15;        // Wl2 16x64
        float4 v = ((const float4*)Wl2)[r * 16 + kk];
        uint2 p;
        p.x = h22u(__floats2half2_rn(v.x, v.y));
        p.y = h22u(__floats2half2_rn(v.z, v.w));
        *(uint2*)(smw + SM_W2 + r * W2_W + 2 * kk) = p;
    }

    // ---- stage edges WARP-LOCALLY into own slots (stride SLOT_W ints)
    int* esI = (int*)smw;
#pragma unroll
    for (int j = 0; j < GPT; j++) {
        int slot = 4 * w + (lane >> 3) + 32 * j;
        int g = gbase + slot; if (g >= B) g = B - 1;
        int v = lane & 7;
        *(int4*)(esI + slot * SLOT_W + v * 4) = ((const int4*)ei)[g * 8 + v];
    }
    // ---- load x for my graphs
    float h0[GPT][2];
#pragma unroll
    for (int j = 0; j < GPT; j++) {
        int g = gbase + q + 32 * j; if (g >= B) g = B - 1;
        float2 xv = ((const float2*)x)[g * 8 + n];
        h0[j][0] = xv.x; h0[j][1] = xv.y;
    }
    __syncwarp();

    // ---- adjacency byte-counts (self-loop folded) + degree (all warp-local reads)
    unsigned c0[GPT], c1[GPT]; float dis[GPT];
#pragma unroll
    for (int j = 0; j < GPT; j++) {
        const int4* eg = (const int4*)(esI + (q + 32 * j) * SLOT_W);
        unsigned a0 = 0, a1 = 0;
#pragma unroll
        for (int e4 = 0; e4 < 4; e4++) {
            int4 rv = eg[e4];        // rows
            int4 cv = eg[4 + e4];    // cols
            {unsigned inc = (unsigned)(cv.x == n) << (8 * (rv.x & 3)); if (rv.x < 4) a0 += inc; else a1 += inc;}
            {unsigned inc = (unsigned)(cv.y == n) << (8 * (rv.y & 3)); if (rv.y < 4) a0 += inc; else a1 += inc;}
            {unsigned inc = (unsigned)(cv.z == n) << (8 * (rv.z & 3)); if (rv.z < 4) a0 += inc; else a1 += inc;}
            {unsigned inc = (unsigned)(cv.w == n) << (8 * (rv.w & 3)); if (rv.w < 4) a0 += inc; else a1 += inc;}
        }
        if (n < 4) a0 += 1u << (8 * n); else a1 += 1u << (8 * (n - 4));
        unsigned deg = __dp4a(a0, 0x01010101u, __dp4a(a1, 0x01010101u, 0u));
        dis[j] = rsqrtf((float)deg);
        c0[j] = a0; c1[j] = a1;
    }
    __syncwarp();    // edge reads done before publishes overwrite the slot words

    // ================= conv layer 1 (Cin=2 -> Cout=4) =================
    // publish x*dis as half2 at word slot*SLOT_W + 8n
#pragma unroll
    for (int j = 0; j < GPT; j++)
        smw[(q + 32 * j) * SLOT_W + 8 * n] =
            h22u(__floats2half2_rn(h0[j][0] * dis[j], h0[j][1] * dis[j]));
    __syncwarp();

    __half2 acc1[GPT];
#pragma unroll
    for (int j = 0; j < GPT; j++) {
        __half2 acc = __float2half2_rn(0.f);
        const unsigned* hg = smw + (q + 32 * j) * SLOT_W;
#pragma unroll
        for (int m = 0; m < 8; m++) {
            __half2 cw = (m < 4) ? cnt2(c0[j], m) : cnt2(c1[j], m - 4);
            acc = __hfma2(cw, u2h2(hg[8 * m]), acc);
        }
        acc1[j] = acc;
    }
    __syncwarp();    // reads done before layer-2 publish

    // matmul W1 + bias + relu + *dis, publish h1*dis (4 halfs)
#pragma unroll
    for (int j = 0; j < GPT; j++) {
        float2 a = __half22float2(acc1[j]);
        float t[4];
#pragma unroll
        for (int c = 0; c < 4; c++) {
            float s = fmaf(cW1[2 * c], a.x, cW1[2 * c + 1] * a.y);
            t[c] = fmaxf(fmaf(dis[j], s, cb1[c]), 0.f) * dis[j];
        }
        uint2 p;
        p.x = h22u(__floats2half2_rn(t[0], t[1]));
        p.y = h22u(__floats2half2_rn(t[2], t[3]));
        *(uint2*)(smw + (q + 32 * j) * SLOT_W + 8 * n) = p;
    }
    __syncwarp();

    // ================= conv layer 2 (Cin=4 -> Cout=8) =================
    __half2 acc2[GPT][2];
#pragma unroll
    for (int j = 0; j < GPT; j++) {
        __half2 s0 = __float2half2_rn(0.f), s1 = s0;
        const unsigned* hg = smw + (q + 32 * j) * SLOT_W;
#pragma unroll
        for (int m = 0; m < 8; m++) {
            __half2 cw = (m < 4) ? cnt2(c0[j], m) : cnt2(c1[j], m - 4);
            uint2 v = *(const uint2*)(hg + 8 * m);
            s0 = __hfma2(cw, u2h2(v.x), s0);
            s1 = __hfma2(cw, u2h2(v.y), s1);
        }
        acc2[j][0] = s0; acc2[j][1] = s1;
    }
    __syncwarp();

#pragma unroll
    for (int j = 0; j < GPT; j++) {
        float2 a01 = __half22float2(acc2[j][0]);
        float2 a23 = __half22float2(acc2[j][1]);
        float a[4] = { a01.x, a01.y, a23.x, a23.y };
        uint4 p;
        float t[8];
#pragma unroll
        for (int c = 0; c < 8; c++) {
            float s = 0.f;
#pragma unroll
            for (int k = 0; k < 4; k++) s = fmaf(cW2[4 * c + k], a[k], s);
            t[c] = fmaxf(fmaf(dis[j], s, cb2[c]), 0.f) * dis[j];
        }
        p.x = h22u(__floats2half2_rn(t[0], t[1]));
        p.y = h22u(__floats2half2_rn(t[2], t[3]));
        p.z = h22u(__floats2half2_rn(t[4], t[5]));
        p.w = h22u(__floats2half2_rn(t[6], t[7]));
        *(uint4*)(smw + (q + 32 * j) * SLOT_W + 8 * n) = p;
    }
    __syncwarp();

    // ================= conv layer 3 (Cin=8 -> Cout=16) -> flat =================
    __half2 acc3[GPT][4];
#pragma unroll
    for (int j = 0; j < GPT; j++) {
        __half2 s0 = __float2half2_rn(0.f), s1 = s0, s2 = s0, s3 = s0;
        const unsigned* hg = smw + (q + 32 * j) * SLOT_W;
#pragma unroll
        for (int m = 0; m < 8; m++) {
            __half2 cw = (m < 4) ? cnt2(c0[j], m) : cnt2(c1[j], m - 4);
            uint4 v = *(const uint4*)(hg + 8 * m);
            s0 = __hfma2(cw, u2h2(v.x), s0);
            s1 = __hfma2(cw, u2h2(v.y), s1);
            s2 = __hfma2(cw, u2h2(v.z), s2);
            s3 = __hfma2(cw, u2h2(v.w), s3);
        }
        acc3[j][0] = s0; acc3[j][1] = s1; acc3[j][2] = s2; acc3[j][3] = s3;
    }
    __syncwarp();

#pragma unroll
    for (int j = 0; j < GPT; j++) {
        float a[8];
#pragma unroll
        for (int p2 = 0; p2 < 4; p2++) {
            float2 f = __half22float2(acc3[j][p2]);
            a[2 * p2] = f.x; a[2 * p2 + 1] = f.y;
        }
        unsigned* dst = smw + (q + 32 * j) * SLOT_W + 8 * n;
        uint4 lo, hi;
        float t[16];
#pragma unroll
        for (int c = 0; c < 16; c++) {
            float s = 0.f;
#pragma unroll
            for (int k = 0; k < 8; k++) s = fmaf(cW3[8 * c + k], a[k], s);
            t[c] = fmaxf(fmaf(dis[j], s, cb3[c]), 0.f);   // flat = h3 (no dis)
        }
        lo.x = h22u(__floats2half2_rn(t[0], t[1]));
        lo.y = h22u(__floats2half2_rn(t[2], t[3]));
        lo.z = h22u(__floats2half2_rn(t[4], t[5]));
        lo.w = h22u(__floats2half2_rn(t[6], t[7]));
        hi.x = h22u(__floats2half2_rn(t[8], t[9]));
        hi.y = h22u(__floats2half2_rn(t[10], t[11]));
        hi.z = h22u(__floats2half2_rn(t[12], t[13]));
        hi.w = h22u(__floats2half2_rn(t[14], t[15]));
        *(uint4*)dst = lo;
        *(uint4*)(dst + 4) = hi;
    }

    __syncthreads();   // the ONE block barrier: weights staged, flat published

    // ======== MLP1 via fp16 mma m16n8k16: warp w owns slots [16w, 16w+16)
    const int grp = lane >> 2;   // 0..7
    const int qd  = lane & 3;    // 0..3
    const unsigned* aBase = smw + (16 * w + grp) * SLOT_W + qd;   // + kc*8 (+4); +8*SLOT_W for rows 8..15
    const unsigned* bBase = smw + SM_W1 + grp * W1_W + qd;        // + (nt*8)*W1_W + kc*8 (+4)

    float d[8][4];
#pragma unroll
    for (int nt = 0; nt < 8; nt++) {
        float cc0 = cbl1[nt * 8 + 2 * qd], cc1 = cbl1[nt * 8 + 2 * qd + 1];
        d[nt][0] = cc0; d[nt][1] = cc1; d[nt][2] = cc0; d[nt][3] = cc1;
    }
#pragma unroll
    for (int kc = 0; kc < 8; kc++) {
        unsigned a0 = aBase[kc * 8];
        unsigned a1 = aBase[8 * SLOT_W + kc * 8];
        unsigned a2 = aBase[kc * 8 + 4];
        unsigned a3 = aBase[8 * SLOT_W + kc * 8 + 4];
#pragma unroll
        for (int nt = 0; nt < 8; nt++) {
            unsigned b0 = bBase[nt * 8 * W1_W + kc * 8];
            unsigned b1 = bBase[nt * 8 * W1_W + kc * 8 + 4];
            mma_f16(d[nt], a0, a1, a2, a3, b0, b1);
        }
    }
    __syncwarp();   // flat reads done before z overwrites slot words 0..31

    // relu + store z as halfs (64 halfs = words 0..31 of own slots)
    unsigned* z0 = smw + (16 * w + grp) * SLOT_W;
    unsigned* z1 = z0 + 8 * SLOT_W;
#pragma unroll
    for (int nt = 0; nt < 8; nt++) {
        z0[nt * 4 + qd] = h22u(__floats2half2_rn(fmaxf(d[nt][0], 0.f), fmaxf(d[nt][1], 0.f)));
        z1[nt * 4 + qd] = h22u(__floats2half2_rn(fmaxf(d[nt][2], 0.f), fmaxf(d[nt][3], 0.f)));
    }
    __syncwarp();

    // ======== MLP2 via fp16 mma: A = Z[16x64], B = Wl2[16x64]
    float e[2][4];
#pragma unroll
    for (int nt = 0; nt < 2; nt++) {
        float cc0 = cbl2[nt * 8 + 2 * qd], cc1 = cbl2[nt * 8 + 2 * qd + 1];
        e[nt][0] = cc0; e[nt][1] = cc1; e[nt][2] = cc0; e[nt][3] = cc1;
    }
    const unsigned* b2Base = smw + SM_W2 + grp * W2_W + qd;
#pragma unroll
    for (int kc = 0; kc < 4; kc++) {
        unsigned a0 = z0[kc * 8 + qd] ;      // word = kc*8 + qd (z words 0..31)
        unsigned a1 = z1[kc * 8 + qd];
        unsigned a2 = z0[kc * 8 + qd + 4];
        unsigned a3 = z1[kc * 8 + qd + 4];
        // NOTE: z0 already includes +0 base (no qd) — addresses: z0 = slot base; need qd offset once:
        // (handled by the +qd in the index above)
#pragma unroll
        for (int nt = 0; nt < 2; nt++) {
            unsigned b0 = b2Base[nt * 8 * W2_W + kc * 8];
            unsigned b1 = b2Base[nt * 8 * W2_W + kc * 8 + 4];
            mma_f16(e[nt], a0, a1, a2, a3, b0, b1);
        }
    }
    // D fragments -> gmem (coalesced float2)
    const int g0 = gbase + 16 * w + grp;
#pragma unroll
    for (int nt = 0; nt < 2; nt++) {
        int col = nt * 8 + 2 * qd;
        if (g0 < B)
            *(float2*)(out + g0 * 16 + col) = make_float2(e[nt][0], e[nt][1]);
        if (g0 + 8 < B)
            *(float2*)(out + (g0 + 8) * 16 + col) = make_float2(e[nt][2], e[nt][3]);
    }
}

extern "C" void kernel_launch(void* const* d_in, const int* in_sizes, int n_in,
                              void* d_out, int out_size)
{
    const float* x  = (const float*)d_in[0];
    const int*   ei = (const int*)d_in[1];
    float* out = (float*)d_out;

    cudaMemcpyToSymbolAsync(cW1,  d_in[2],   8 * 4, 0, cudaMemcpyDeviceToDevice);
    cudaMemcpyToSymbolAsync(cb1,  d_in[3],   4 * 4, 0, cudaMemcpyDeviceToDevice);
    cudaMemcpyToSymbolAsync(cW2,  d_in[4],  32 * 4, 0, cudaMemcpyDeviceToDevice);
    cudaMemcpyToSymbolAsync(cb2,  d_in[5],   8 * 4, 0, cudaMemcpyDeviceToDevice);
    cudaMemcpyToSymbolAsync(cW3,  d_in[6], 128 * 4, 0, cudaMemcpyDeviceToDevice);
    cudaMemcpyToSymbolAsync(cb3,  d_in[7],  16 * 4, 0, cudaMemcpyDeviceToDevice);
    cudaMemcpyToSymbolAsync(cbl1, d_in[9],  64 * 4, 0, cudaMemcpyDeviceToDevice);
    cudaMemcpyToSymbolAsync(cbl2, d_in[11], 16 * 4, 0, cudaMemcpyDeviceToDevice);

    const int B = in_sizes[0] / 16;   // x is [B, 8, 2]
    const int grid = (B + GPB - 1) / GPB;

    cudaFuncSetAttribute(gnn_kernel, cudaFuncAttributeMaxDynamicSharedMemorySize, SMEM_BYTES);
    gnn_kernel<<<grid, NTHREADS, SMEM_BYTES>>>(x, ei, (const float*)d_in[8],
                                               (const float*)d_in[10], out, B);
}